// round 3
// baseline (speedup 1.0000x reference)
#include <cuda_runtime.h>

#define N_NODES 100000
#define N_EDGES 1600000
#define NUM_G   256
#define D_IN    128
#define D       64
#define BN_EPS  1e-5f

// ---------------- scratch (device globals; no allocation allowed) ----------
__device__ int   g_count[N_NODES];        // in-degree (excl self loop)
__device__ int   g_fill[N_NODES];         // fill cursors for CSR build
__device__ int   g_rowptr[N_NODES + 1];
__device__ int   g_csr[N_EDGES];          // src node per in-edge, grouped by dst
__device__ float g_dinv[N_NODES];
__device__ float g_hs[N_NODES * D];       // (act @ W) * dinv[row]
__device__ float g_act[N_NODES * D];      // pre-BN layer output
__device__ float g_stats[2 * D];          // column sum, sumsq
__device__ float g_s[D];                  // BN scale
__device__ float g_t[D];                  // BN shift
__device__ float g_pool[NUM_G * D];
__device__ int   g_gcnt[NUM_G];

// ---------------- init: zero all per-launch state --------------------------
__global__ void k_init() {
    int stride = gridDim.x * blockDim.x;
    for (int i = blockIdx.x * blockDim.x + threadIdx.x; i < N_NODES; i += stride) {
        g_count[i] = 0;
        g_fill[i]  = 0;
        if (i < NUM_G * D) g_pool[i] = 0.f;
        if (i < NUM_G)     g_gcnt[i] = 0;
    }
}

// ---------------- degree histogram + graph-size histogram -------------------
__global__ void k_count(const int* __restrict__ dst) {
    int e = blockIdx.x * blockDim.x + threadIdx.x;
    if (e < N_EDGES) atomicAdd(&g_count[dst[e]], 1);
}

__global__ void k_gcnt(const int* __restrict__ batch) {
    int i = blockIdx.x * blockDim.x + threadIdx.x;
    if (i < N_NODES) atomicAdd(&g_gcnt[batch[i]], 1);
}

// ---------------- single-block exclusive scan over g_count ------------------
__global__ void k_scan() {
    __shared__ int warpsums[32];
    __shared__ int carry_sh;
    int tid  = threadIdx.x;
    int lane = tid & 31, wid = tid >> 5;
    if (tid == 0) carry_sh = 0;
    __syncthreads();
    for (int base = 0; base < N_NODES; base += 1024) {
        int i = base + tid;
        int v = (i < N_NODES) ? g_count[i] : 0;
        int x = v;
        #pragma unroll
        for (int d = 1; d < 32; d <<= 1) {
            int y = __shfl_up_sync(0xffffffffu, x, d);
            if (lane >= d) x += y;
        }
        if (lane == 31) warpsums[wid] = x;
        __syncthreads();
        if (wid == 0) {
            int s = warpsums[lane];
            #pragma unroll
            for (int d = 1; d < 32; d <<= 1) {
                int y = __shfl_up_sync(0xffffffffu, s, d);
                if (lane >= d) s += y;
            }
            warpsums[lane] = s;
        }
        __syncthreads();
        int incl  = x + (wid > 0 ? warpsums[wid - 1] : 0);
        int total = warpsums[31];
        if (i < N_NODES) g_rowptr[i] = carry_sh + (incl - v);
        __syncthreads();
        if (tid == 0) carry_sh += total;
        __syncthreads();
    }
    if (threadIdx.x == 0) g_rowptr[N_NODES] = carry_sh;
}

// ---------------- CSR fill + dinv -------------------------------------------
__global__ void k_fill(const int* __restrict__ src,
                       const int* __restrict__ dst) {
    int e = blockIdx.x * blockDim.x + threadIdx.x;
    if (e < N_EDGES) {
        int d = dst[e];
        int p = g_rowptr[d] + atomicAdd(&g_fill[d], 1);
        g_csr[p] = src[e];
    }
}

__global__ void k_dinv() {
    int i = blockIdx.x * blockDim.x + threadIdx.x;
    if (i < N_NODES) g_dinv[i] = rsqrtf((float)(g_count[i] + 1));
}

// ---------------- GEMM: hs = BN?(act) @ W * dinv[row] -----------------------
// 64-node x 64-col tile, 256 threads, each thread a 4x4 micro-tile.
template <int KDIM, bool APPLY_BN>
__global__ void k_gemm(const float* __restrict__ act_in,
                       const float* __restrict__ W) {
    __shared__ float As[64 * 65];
    __shared__ float Ws[64 * 64];
    const float* act = APPLY_BN ? (const float*)g_act : act_in;

    int tid = threadIdx.x;
    int tx = tid & 15, ty = tid >> 4;
    int row0 = blockIdx.x * 64;

    float acc[4][4];
    #pragma unroll
    for (int j = 0; j < 4; j++)
        #pragma unroll
        for (int c = 0; c < 4; c++) acc[j][c] = 0.f;

    for (int kc = 0; kc < KDIM; kc += 64) {
        // stage act tile (apply BN+ReLU of previous layer on load)
        for (int idx = tid; idx < 64 * 64; idx += 256) {
            int r = idx >> 6, k = idx & 63;
            int row = row0 + r;
            float v = 0.f;
            if (row < N_NODES) {
                v = act[row * KDIM + kc + k];
                if (APPLY_BN) v = fmaxf(v * g_s[kc + k] + g_t[kc + k], 0.f);
            }
            As[r * 65 + k] = v;
        }
        // stage W tile
        for (int idx = tid; idx < 64 * 64; idx += 256) {
            int k = idx >> 6, c = idx & 63;
            Ws[idx] = W[(kc + k) * D + c];
        }
        __syncthreads();
        #pragma unroll 8
        for (int k = 0; k < 64; k++) {
            float a0 = As[(ty * 4 + 0) * 65 + k];
            float a1 = As[(ty * 4 + 1) * 65 + k];
            float a2 = As[(ty * 4 + 2) * 65 + k];
            float a3 = As[(ty * 4 + 3) * 65 + k];
            float4 bv = *(const float4*)&Ws[k * 64 + tx * 4];
            acc[0][0] += a0 * bv.x; acc[0][1] += a0 * bv.y; acc[0][2] += a0 * bv.z; acc[0][3] += a0 * bv.w;
            acc[1][0] += a1 * bv.x; acc[1][1] += a1 * bv.y; acc[1][2] += a1 * bv.z; acc[1][3] += a1 * bv.w;
            acc[2][0] += a2 * bv.x; acc[2][1] += a2 * bv.y; acc[2][2] += a2 * bv.z; acc[2][3] += a2 * bv.w;
            acc[3][0] += a3 * bv.x; acc[3][1] += a3 * bv.y; acc[3][2] += a3 * bv.z; acc[3][3] += a3 * bv.w;
        }
        __syncthreads();
    }
    #pragma unroll
    for (int j = 0; j < 4; j++) {
        int row = row0 + ty * 4 + j;
        if (row < N_NODES) {
            float di = g_dinv[row];
            float4 o = make_float4(acc[j][0] * di, acc[j][1] * di,
                                   acc[j][2] * di, acc[j][3] * di);
            *(float4*)&g_hs[row * D + tx * 4] = o;
        }
    }
}

// ---------------- zero stats -------------------------------------------------
__global__ void k_zero_stats() { g_stats[threadIdx.x] = 0.f; }

// ---------------- aggregation: warp per node, gather over CSR ---------------
// acc = hs[i] (self loop) + sum over in-edges hs[src]; out = acc*dinv[i]+b.
// Also accumulates per-column BN stats.
__global__ void k_agg(const float* __restrict__ bias) {
    int tid  = threadIdx.x;
    int lane = tid & 31;
    int gw   = (blockIdx.x * blockDim.x + tid) >> 5;
    int nw   = (gridDim.x * blockDim.x) >> 5;

    float b0 = bias[lane * 2];
    float b1 = bias[lane * 2 + 1];
    float s0 = 0.f, s1 = 0.f, q0 = 0.f, q1 = 0.f;

    for (int i = gw; i < N_NODES; i += nw) {
        float2 acc = *(const float2*)&g_hs[i * D + lane * 2];  // self loop
        int rs = g_rowptr[i], re = g_rowptr[i + 1];
        for (int eb = rs; eb < re; eb += 32) {
            int myi = (eb + lane < re) ? g_csr[eb + lane] : 0;
            int cnt = min(32, re - eb);
            for (int j = 0; j < cnt; j++) {
                int s = __shfl_sync(0xffffffffu, myi, j);
                float2 v = *(const float2*)&g_hs[s * D + lane * 2];
                acc.x += v.x; acc.y += v.y;
            }
        }
        float di = g_dinv[i];
        float o0 = acc.x * di + b0;
        float o1 = acc.y * di + b1;
        *(float2*)&g_act[i * D + lane * 2] = make_float2(o0, o1);
        s0 += o0; s1 += o1; q0 += o0 * o0; q1 += o1 * o1;
    }

    __shared__ float ssum[2 * D];
    if (tid < 2 * D) ssum[tid] = 0.f;
    __syncthreads();
    atomicAdd(&ssum[lane * 2],     s0);
    atomicAdd(&ssum[lane * 2 + 1], s1);
    atomicAdd(&ssum[D + lane * 2],     q0);
    atomicAdd(&ssum[D + lane * 2 + 1], q1);
    __syncthreads();
    if (tid < 2 * D) atomicAdd(&g_stats[tid], ssum[tid]);
}

// ---------------- BN scale/shift from stats ---------------------------------
__global__ void k_st(const float* __restrict__ gamma,
                     const float* __restrict__ beta) {
    int c = threadIdx.x;
    float inv_n = 1.f / (float)N_NODES;
    float mean = g_stats[c] * inv_n;
    float var  = g_stats[D + c] * inv_n - mean * mean;
    float sc = gamma[c] * rsqrtf(var + BN_EPS);
    g_s[c] = sc;
    g_t[c] = beta[c] - mean * sc;
}

// ---------------- pooling: segmented accumulation (batch is sorted) ---------
#define POOL_CHUNK 256
__global__ void k_pool(const int* __restrict__ batch) {
    int c    = threadIdx.x;   // 64 threads, one per column
    int base = blockIdx.x * POOL_CHUNK;
    int end  = min(base + POOL_CHUNK, N_NODES);
    float sc = g_s[c], tc = g_t[c];
    float acc = 0.f;
    int curg = -1;
    for (int n = base; n < end; n++) {
        int g = batch[n];
        float v = fmaxf(g_act[n * D + c] * sc + tc, 0.f);
        if (g != curg) {
            if (curg >= 0) atomicAdd(&g_pool[curg * D + c], acc);
            acc = 0.f; curg = g;
        }
        acc += v;
    }
    if (curg >= 0) atomicAdd(&g_pool[curg * D + c], acc);
}

__global__ void k_final(float* __restrict__ out) {
    int idx = blockIdx.x * blockDim.x + threadIdx.x;
    if (idx < NUM_G * D) {
        int g = idx >> 6;
        out[idx] = g_pool[idx] / fmaxf((float)g_gcnt[g], 1.f);
    }
}

// ---------------- host launch ------------------------------------------------
extern "C" void kernel_launch(void* const* d_in, const int* in_sizes, int n_in,
                              void* d_out, int out_size) {
    const float* x     = (const float*)d_in[0];
    const int*   ei    = (const int*)d_in[1];   // [2, E] int32
    const int*   batch = (const int*)d_in[3];
    const float* W1 = (const float*)d_in[4];
    const float* b1 = (const float*)d_in[5];
    const float* g1 = (const float*)d_in[6];
    const float* be1 = (const float*)d_in[7];
    const float* W2 = (const float*)d_in[8];
    const float* b2 = (const float*)d_in[9];
    const float* g2 = (const float*)d_in[10];
    const float* be2 = (const float*)d_in[11];
    const float* W3 = (const float*)d_in[12];
    const float* b3 = (const float*)d_in[13];
    const float* g3 = (const float*)d_in[14];
    const float* be3 = (const float*)d_in[15];
    float* out = (float*)d_out;

    const int* src = ei;
    const int* dst = ei + N_EDGES;

    const int EB = (N_EDGES + 255) / 256;
    const int NB = (N_NODES + 255) / 256;
    const int GEMM_B = (N_NODES + 63) / 64;

    k_init<<<512, 256>>>();
    k_count<<<EB, 256>>>(dst);
    k_gcnt<<<NB, 256>>>(batch);
    k_scan<<<1, 1024>>>();
    k_fill<<<EB, 256>>>(src, dst);
    k_dinv<<<NB, 256>>>();

    // layer 1
    k_gemm<D_IN, false><<<GEMM_B, 256>>>(x, W1);
    k_zero_stats<<<1, 128>>>();
    k_agg<<<2048, 256>>>(b1);
    k_st<<<1, 64>>>(g1, be1);

    // layer 2
    k_gemm<D, true><<<GEMM_B, 256>>>(nullptr, W2);
    k_zero_stats<<<1, 128>>>();
    k_agg<<<2048, 256>>>(b2);
    k_st<<<1, 64>>>(g2, be2);

    // layer 3
    k_gemm<D, true><<<GEMM_B, 256>>>(nullptr, W3);
    k_zero_stats<<<1, 128>>>();
    k_agg<<<2048, 256>>>(b3);
    k_st<<<1, 64>>>(g3, be3);

    // pool + finalize
    k_pool<<<(N_NODES + POOL_CHUNK - 1) / POOL_CHUNK, 64>>>(batch);
    k_final<<<(NUM_G * D + 255) / 256, 256>>>(out);
}

// round 4
// speedup vs baseline: 1.5056x; 1.5056x over previous
#include <cuda_runtime.h>
#include <cuda_fp16.h>

#define N_NODES 100000
#define N_EDGES 1600000
#define NUM_G   256
#define D_IN    128
#define D       64
#define BN_EPS  1e-5f

#define SCAN_TILE 1024
#define NSB ((N_NODES + SCAN_TILE - 1) / SCAN_TILE)   // 98 scan blocks

// ---------------- scratch (device globals; no allocation allowed) ----------
__device__ int     g_count[N_NODES];       // in-degree (excl self loop)
__device__ int     g_fill[N_NODES];        // fill cursors for CSR build
__device__ int     g_rowptr[N_NODES + 1];
__device__ int     g_bsum[NSB + 1];        // block sums / offsets for scan
__device__ int     g_csr[N_EDGES];         // src node per in-edge, grouped by dst
__device__ float   g_dinv[N_NODES];
__device__ __half2 g_hs[N_NODES * (D/2)];  // (act @ W) * dinv[row], fp16
__device__ float   g_act[N_NODES * D];     // pre-BN layer output (fp32)
__device__ float   g_stats[2 * D];         // column sum, sumsq
__device__ float   g_s[D];                 // BN scale
__device__ float   g_t[D];                 // BN shift
__device__ float   g_pool[NUM_G * D];
__device__ int     g_gcnt[NUM_G];

// ---------------- init: zero all per-launch state --------------------------
__global__ void k_init() {
    int stride = gridDim.x * blockDim.x;
    for (int i = blockIdx.x * blockDim.x + threadIdx.x; i < N_NODES; i += stride) {
        g_count[i] = 0;
        g_fill[i]  = 0;
        if (i < NUM_G * D) g_pool[i] = 0.f;
        if (i < NUM_G)     g_gcnt[i] = 0;
        if (i < 2 * D)     g_stats[i] = 0.f;
    }
}

// ---------------- degree histogram + graph-size histogram -------------------
__global__ void k_count(const int* __restrict__ dst) {
    int e = blockIdx.x * blockDim.x + threadIdx.x;
    if (e < N_EDGES) atomicAdd(&g_count[dst[e]], 1);
}

__global__ void k_gcnt(const int* __restrict__ batch) {
    int i = blockIdx.x * blockDim.x + threadIdx.x;
    if (i < N_NODES) atomicAdd(&g_gcnt[batch[i]], 1);
}

// ---------------- 3-phase multi-block scan -----------------------------------
// phase 1: each block scans its 1024-element tile (exclusive), emits block sum
__global__ void k_scan1() {
    __shared__ int wsum[32];
    int tid = threadIdx.x, lane = tid & 31, wid = tid >> 5;
    int i = blockIdx.x * SCAN_TILE + tid;
    int v = (i < N_NODES) ? g_count[i] : 0;
    int x = v;
    #pragma unroll
    for (int d = 1; d < 32; d <<= 1) {
        int y = __shfl_up_sync(0xffffffffu, x, d);
        if (lane >= d) x += y;
    }
    if (lane == 31) wsum[wid] = x;
    __syncthreads();
    if (wid == 0) {
        int s = wsum[lane];
        #pragma unroll
        for (int d = 1; d < 32; d <<= 1) {
            int y = __shfl_up_sync(0xffffffffu, s, d);
            if (lane >= d) s += y;
        }
        wsum[lane] = s;
    }
    __syncthreads();
    int excl = x - v + (wid > 0 ? wsum[wid - 1] : 0);
    if (i < N_NODES) g_rowptr[i] = excl;
    if (tid == 0) g_bsum[blockIdx.x] = wsum[31];
}

// phase 2: single small block scans the 98 block sums (exclusive), plus total
__global__ void k_scan2() {
    __shared__ int wsum[4];
    int tid = threadIdx.x, lane = tid & 31, wid = tid >> 5;  // 128 threads
    int v = (tid < NSB) ? g_bsum[tid] : 0;
    int x = v;
    #pragma unroll
    for (int d = 1; d < 32; d <<= 1) {
        int y = __shfl_up_sync(0xffffffffu, x, d);
        if (lane >= d) x += y;
    }
    if (lane == 31) wsum[wid] = x;
    __syncthreads();
    if (tid == 0) {
        int c = 0;
        #pragma unroll
        for (int w = 0; w < 4; w++) { int t = wsum[w]; wsum[w] = c; c += t; }
    }
    __syncthreads();
    int excl = x - v + wsum[wid];
    if (tid < NSB) g_bsum[tid] = excl;
    if (tid == NSB - 1) g_bsum[NSB] = excl + v;  // total
}

// phase 3: add block offsets; fuse dinv; write rowptr[N]
__global__ void k_scan3() {
    int i = blockIdx.x * blockDim.x + threadIdx.x;
    if (i < N_NODES) {
        g_rowptr[i] += g_bsum[i >> 10];
        g_dinv[i] = rsqrtf((float)(g_count[i] + 1));
    }
    if (i == 0) g_rowptr[N_NODES] = g_bsum[NSB];
}

// ---------------- CSR fill ---------------------------------------------------
__global__ void k_fill(const int* __restrict__ src,
                       const int* __restrict__ dst) {
    int e = blockIdx.x * blockDim.x + threadIdx.x;
    if (e < N_EDGES) {
        int d = dst[e];
        int p = g_rowptr[d] + atomicAdd(&g_fill[d], 1);
        g_csr[p] = src[e];
    }
}

// ---------------- GEMM: hs = BN?(act) @ W * dinv[row], stored fp16 ----------
// 64-node x 64-col tile, 256 threads, each thread a 4x4 micro-tile.
template <int KDIM, bool APPLY_BN>
__global__ void k_gemm(const float* __restrict__ act_in,
                       const float* __restrict__ W) {
    __shared__ float As[64 * 65];
    __shared__ float Ws[64 * 64];
    const float* act = APPLY_BN ? (const float*)g_act : act_in;

    int tid = threadIdx.x;
    int tx = tid & 15, ty = tid >> 4;
    int row0 = blockIdx.x * 64;

    float acc[4][4];
    #pragma unroll
    for (int j = 0; j < 4; j++)
        #pragma unroll
        for (int c = 0; c < 4; c++) acc[j][c] = 0.f;

    for (int kc = 0; kc < KDIM; kc += 64) {
        for (int idx = tid; idx < 64 * 64; idx += 256) {
            int r = idx >> 6, k = idx & 63;
            int row = row0 + r;
            float v = 0.f;
            if (row < N_NODES) {
                v = act[row * KDIM + kc + k];
                if (APPLY_BN) v = fmaxf(v * g_s[kc + k] + g_t[kc + k], 0.f);
            }
            As[r * 65 + k] = v;
        }
        for (int idx = tid; idx < 64 * 64; idx += 256) {
            int k = idx >> 6, c = idx & 63;
            Ws[idx] = W[(kc + k) * D + c];
        }
        __syncthreads();
        #pragma unroll 8
        for (int k = 0; k < 64; k++) {
            float a0 = As[(ty * 4 + 0) * 65 + k];
            float a1 = As[(ty * 4 + 1) * 65 + k];
            float a2 = As[(ty * 4 + 2) * 65 + k];
            float a3 = As[(ty * 4 + 3) * 65 + k];
            float4 bv = *(const float4*)&Ws[k * 64 + tx * 4];
            acc[0][0] += a0 * bv.x; acc[0][1] += a0 * bv.y; acc[0][2] += a0 * bv.z; acc[0][3] += a0 * bv.w;
            acc[1][0] += a1 * bv.x; acc[1][1] += a1 * bv.y; acc[1][2] += a1 * bv.z; acc[1][3] += a1 * bv.w;
            acc[2][0] += a2 * bv.x; acc[2][1] += a2 * bv.y; acc[2][2] += a2 * bv.z; acc[2][3] += a2 * bv.w;
            acc[3][0] += a3 * bv.x; acc[3][1] += a3 * bv.y; acc[3][2] += a3 * bv.z; acc[3][3] += a3 * bv.w;
        }
        __syncthreads();
    }
    #pragma unroll
    for (int j = 0; j < 4; j++) {
        int row = row0 + ty * 4 + j;
        if (row < N_NODES) {
            float di = g_dinv[row];
            union { __half2 h[2]; uint2 u; } pk;
            pk.h[0] = __floats2half2_rn(acc[j][0] * di, acc[j][1] * di);
            pk.h[1] = __floats2half2_rn(acc[j][2] * di, acc[j][3] * di);
            *(uint2*)&g_hs[row * (D/2) + tx * 2] = pk.u;
        }
    }
}

// ---------------- aggregation: warp per node, gather over CSR (fp16 reads) --
__global__ void k_agg(const float* __restrict__ bias) {
    int tid  = threadIdx.x;
    int lane = tid & 31;
    int gw   = (blockIdx.x * blockDim.x + tid) >> 5;
    int nw   = (gridDim.x * blockDim.x) >> 5;

    float b0 = bias[lane * 2];
    float b1 = bias[lane * 2 + 1];
    float s0 = 0.f, s1 = 0.f, q0 = 0.f, q1 = 0.f;

    for (int i = gw; i < N_NODES; i += nw) {
        float2 acc = __half22float2(g_hs[i * (D/2) + lane]);  // self loop
        int rs = g_rowptr[i], re = g_rowptr[i + 1];
        int eb = rs;
        // full 32-edge chunks: compile-time unrolled -> batched LDGs
        for (; eb + 32 <= re; eb += 32) {
            int myi = g_csr[eb + lane];
            #pragma unroll
            for (int j = 0; j < 32; j++) {
                int s = __shfl_sync(0xffffffffu, myi, j);
                float2 v = __half22float2(g_hs[s * (D/2) + lane]);
                acc.x += v.x; acc.y += v.y;
            }
        }
        // remainder
        if (eb < re) {
            int myi = (eb + lane < re) ? g_csr[eb + lane] : 0;
            int cnt = re - eb;
            for (int j = 0; j < cnt; j++) {
                int s = __shfl_sync(0xffffffffu, myi, j);
                float2 v = __half22float2(g_hs[s * (D/2) + lane]);
                acc.x += v.x; acc.y += v.y;
            }
        }
        float di = g_dinv[i];
        float o0 = acc.x * di + b0;
        float o1 = acc.y * di + b1;
        *(float2*)&g_act[i * D + lane * 2] = make_float2(o0, o1);
        s0 += o0; s1 += o1; q0 += o0 * o0; q1 += o1 * o1;
    }

    __shared__ float ssum[2 * D];
    if (tid < 2 * D) ssum[tid] = 0.f;
    __syncthreads();
    atomicAdd(&ssum[lane * 2],     s0);
    atomicAdd(&ssum[lane * 2 + 1], s1);
    atomicAdd(&ssum[D + lane * 2],     q0);
    atomicAdd(&ssum[D + lane * 2 + 1], q1);
    __syncthreads();
    if (tid < 2 * D) atomicAdd(&g_stats[tid], ssum[tid]);
}

// ---------------- BN scale/shift from stats (also re-zeroes stats) ----------
__global__ void k_st(const float* __restrict__ gamma,
                     const float* __restrict__ beta) {
    int c = threadIdx.x;
    float inv_n = 1.f / (float)N_NODES;
    float mean = g_stats[c] * inv_n;
    float var  = g_stats[D + c] * inv_n - mean * mean;
    float sc = gamma[c] * rsqrtf(var + BN_EPS);
    g_s[c] = sc;
    g_t[c] = beta[c] - mean * sc;
    g_stats[c] = 0.f;
    g_stats[D + c] = 0.f;
}

// ---------------- pooling: segmented accumulation (batch is sorted) ---------
#define POOL_CHUNK 256
__global__ void k_pool(const int* __restrict__ batch) {
    int c    = threadIdx.x;   // 64 threads, one per column
    int base = blockIdx.x * POOL_CHUNK;
    int end  = min(base + POOL_CHUNK, N_NODES);
    float sc = g_s[c], tc = g_t[c];
    float acc = 0.f;
    int curg = -1;
    for (int n = base; n < end; n++) {
        int g = batch[n];
        float v = fmaxf(g_act[n * D + c] * sc + tc, 0.f);
        if (g != curg) {
            if (curg >= 0) atomicAdd(&g_pool[curg * D + c], acc);
            acc = 0.f; curg = g;
        }
        acc += v;
    }
    if (curg >= 0) atomicAdd(&g_pool[curg * D + c], acc);
}

__global__ void k_final(float* __restrict__ out) {
    int idx = blockIdx.x * blockDim.x + threadIdx.x;
    if (idx < NUM_G * D) {
        int g = idx >> 6;
        out[idx] = g_pool[idx] / fmaxf((float)g_gcnt[g], 1.f);
    }
}

// ---------------- host launch ------------------------------------------------
extern "C" void kernel_launch(void* const* d_in, const int* in_sizes, int n_in,
                              void* d_out, int out_size) {
    const float* x     = (const float*)d_in[0];
    const int*   ei    = (const int*)d_in[1];   // [2, E] int32
    const int*   batch = (const int*)d_in[3];
    const float* W1 = (const float*)d_in[4];
    const float* b1 = (const float*)d_in[5];
    const float* g1 = (const float*)d_in[6];
    const float* be1 = (const float*)d_in[7];
    const float* W2 = (const float*)d_in[8];
    const float* b2 = (const float*)d_in[9];
    const float* g2 = (const float*)d_in[10];
    const float* be2 = (const float*)d_in[11];
    const float* W3 = (const float*)d_in[12];
    const float* b3 = (const float*)d_in[13];
    const float* g3 = (const float*)d_in[14];
    const float* be3 = (const float*)d_in[15];
    float* out = (float*)d_out;

    const int* src = ei;
    const int* dst = ei + N_EDGES;

    const int EB = (N_EDGES + 255) / 256;
    const int NB = (N_NODES + 255) / 256;
    const int GEMM_B = (N_NODES + 63) / 64;

    k_init<<<512, 256>>>();
    k_count<<<EB, 256>>>(dst);
    k_gcnt<<<NB, 256>>>(batch);
    k_scan1<<<NSB, SCAN_TILE>>>();
    k_scan2<<<1, 128>>>();
    k_scan3<<<NB, 256>>>();
    k_fill<<<EB, 256>>>(src, dst);

    // layer 1
    k_gemm<D_IN, false><<<GEMM_B, 256>>>(x, W1);
    k_agg<<<2048, 256>>>(b1);
    k_st<<<1, 64>>>(g1, be1);

    // layer 2
    k_gemm<D, true><<<GEMM_B, 256>>>(nullptr, W2);
    k_agg<<<2048, 256>>>(b2);
    k_st<<<1, 64>>>(g2, be2);

    // layer 3
    k_gemm<D, true><<<GEMM_B, 256>>>(nullptr, W3);
    k_agg<<<2048, 256>>>(b3);
    k_st<<<1, 64>>>(g3, be3);

    // pool + finalize
    k_pool<<<(N_NODES + POOL_CHUNK - 1) / POOL_CHUNK, 64>>>(batch);
    k_final<<<(NUM_G * D + 255) / 256, 256>>>(out);
}

// round 5
// speedup vs baseline: 2.0426x; 1.3567x over previous
#include <cuda_runtime.h>
#include <cuda_fp16.h>
#include <mma.h>

#define N_NODES 100000
#define N_EDGES 1600000
#define NUM_G   256
#define D_IN    128
#define D       64
#define BN_EPS  1e-5f

#define SCAN_TILE 1024
#define NSB ((N_NODES + SCAN_TILE - 1) / SCAN_TILE)   // 98 scan blocks

// ---------------- scratch (device globals; no allocation allowed) ----------
__device__ int     g_count[N_NODES];       // in-degree (excl self loop)
__device__ int     g_fill[N_NODES];        // fill cursors for CSR build
__device__ int     g_rowptr[N_NODES + 1];
__device__ int     g_bsum[NSB + 1];        // block sums / offsets for scan
__device__ int     g_csr[N_EDGES];         // src node per in-edge, grouped by dst
__device__ float   g_dinv[N_NODES];
__device__ __half2 g_hs[N_NODES * (D/2)];  // (act @ W) * dinv[row], fp16
__device__ float   g_act[N_NODES * D];     // pre-BN layer output (fp32)
__device__ float   g_stats[2 * D];         // column sum, sumsq
__device__ float   g_s[D];                 // BN scale
__device__ float   g_t[D];                 // BN shift
__device__ float   g_pool[NUM_G * D];
__device__ int     g_gcnt[NUM_G];

// ---------------- init: zero all per-launch state --------------------------
__global__ void k_init() {
    int stride = gridDim.x * blockDim.x;
    for (int i = blockIdx.x * blockDim.x + threadIdx.x; i < N_NODES; i += stride) {
        g_count[i] = 0;
        g_fill[i]  = 0;
        if (i < NUM_G * D) g_pool[i] = 0.f;
        if (i < NUM_G)     g_gcnt[i] = 0;
        if (i < 2 * D)     g_stats[i] = 0.f;
    }
}

// ---------------- degree histogram + graph-size histogram -------------------
__global__ void k_count(const int* __restrict__ dst) {
    int e = blockIdx.x * blockDim.x + threadIdx.x;
    if (e < N_EDGES) atomicAdd(&g_count[dst[e]], 1);
}

__global__ void k_gcnt(const int* __restrict__ batch) {
    int i = blockIdx.x * blockDim.x + threadIdx.x;
    if (i < N_NODES) atomicAdd(&g_gcnt[batch[i]], 1);
}

// ---------------- 3-phase multi-block scan -----------------------------------
__global__ void k_scan1() {
    __shared__ int wsum[32];
    int tid = threadIdx.x, lane = tid & 31, wid = tid >> 5;
    int i = blockIdx.x * SCAN_TILE + tid;
    int v = (i < N_NODES) ? g_count[i] : 0;
    int x = v;
    #pragma unroll
    for (int d = 1; d < 32; d <<= 1) {
        int y = __shfl_up_sync(0xffffffffu, x, d);
        if (lane >= d) x += y;
    }
    if (lane == 31) wsum[wid] = x;
    __syncthreads();
    if (wid == 0) {
        int s = wsum[lane];
        #pragma unroll
        for (int d = 1; d < 32; d <<= 1) {
            int y = __shfl_up_sync(0xffffffffu, s, d);
            if (lane >= d) s += y;
        }
        wsum[lane] = s;
    }
    __syncthreads();
    int excl = x - v + (wid > 0 ? wsum[wid - 1] : 0);
    if (i < N_NODES) g_rowptr[i] = excl;
    if (tid == 0) g_bsum[blockIdx.x] = wsum[31];
}

__global__ void k_scan2() {
    __shared__ int wsum[4];
    int tid = threadIdx.x, lane = tid & 31, wid = tid >> 5;  // 128 threads
    int v = (tid < NSB) ? g_bsum[tid] : 0;
    int x = v;
    #pragma unroll
    for (int d = 1; d < 32; d <<= 1) {
        int y = __shfl_up_sync(0xffffffffu, x, d);
        if (lane >= d) x += y;
    }
    if (lane == 31) wsum[wid] = x;
    __syncthreads();
    if (tid == 0) {
        int c = 0;
        #pragma unroll
        for (int w = 0; w < 4; w++) { int t = wsum[w]; wsum[w] = c; c += t; }
    }
    __syncthreads();
    int excl = x - v + wsum[wid];
    if (tid < NSB) g_bsum[tid] = excl;
    if (tid == NSB - 1) g_bsum[NSB] = excl + v;  // total
}

__global__ void k_scan3() {
    int i = blockIdx.x * blockDim.x + threadIdx.x;
    if (i < N_NODES) {
        g_rowptr[i] += g_bsum[i >> 10];
        g_dinv[i] = rsqrtf((float)(g_count[i] + 1));
    }
    if (i == 0) g_rowptr[N_NODES] = g_bsum[NSB];
}

// ---------------- CSR fill ---------------------------------------------------
__global__ void k_fill(const int* __restrict__ src,
                       const int* __restrict__ dst) {
    int e = blockIdx.x * blockDim.x + threadIdx.x;
    if (e < N_EDGES) {
        int d = dst[e];
        int p = g_rowptr[d] + atomicAdd(&g_fill[d], 1);
        g_csr[p] = src[e];
    }
}

// ---------------- GEMM (wmma fp16->fp32): hs = BN?(act) @ W * dinv[row] -----
// 64-row x 64-col tile per block, 256 threads (8 warps, 4x2 warp grid).
#define LDH 72   // padded half leading dim (144B, mult of 16B)
template <int KDIM, bool APPLY_BN>
__global__ void k_gemm(const float* __restrict__ act_in,
                       const float* __restrict__ W) {
    using namespace nvcuda;
    __shared__ __align__(16) __half As[64 * LDH];
    __shared__ __align__(16) __half Ws[64 * LDH];
    __shared__ __align__(16) float  Cs[64 * 64];
    const float* act = APPLY_BN ? (const float*)g_act : act_in;

    int tid = threadIdx.x;
    int wid = tid >> 5;
    int wr = wid >> 1;      // warp row tile: rows [wr*16, wr*16+16)
    int wc = wid & 1;       // warp col half: cols [wc*32, wc*32+32)
    int row0 = blockIdx.x * 64;

    wmma::fragment<wmma::accumulator, 16, 16, 16, float> c0, c1;
    wmma::fill_fragment(c0, 0.f);
    wmma::fill_fragment(c1, 0.f);

    for (int kc = 0; kc < KDIM; kc += 64) {
        // stage A tile: 64 rows x 64 k, fp32->half, BN+ReLU applied on load
        for (int idx = tid; idx < 64 * 32; idx += 256) {
            int r = idx >> 5, kk = (idx & 31) * 2;
            int row = row0 + r;
            float2 v = make_float2(0.f, 0.f);
            if (row < N_NODES) {
                v = *(const float2*)&act[row * KDIM + kc + kk];
                if (APPLY_BN) {
                    v.x = fmaxf(v.x * g_s[kc + kk]     + g_t[kc + kk],     0.f);
                    v.y = fmaxf(v.y * g_s[kc + kk + 1] + g_t[kc + kk + 1], 0.f);
                }
            }
            *(__half2*)&As[r * LDH + kk] = __floats2half2_rn(v.x, v.y);
        }
        // stage W tile: 64 k x 64 cols
        for (int idx = tid; idx < 64 * 32; idx += 256) {
            int k = idx >> 5, cc = (idx & 31) * 2;
            float2 v = *(const float2*)&W[(kc + k) * D + cc];
            *(__half2*)&Ws[k * LDH + cc] = __floats2half2_rn(v.x, v.y);
        }
        __syncthreads();

        #pragma unroll
        for (int ks = 0; ks < 64; ks += 16) {
            wmma::fragment<wmma::matrix_a, 16, 16, 16, __half, wmma::row_major> a;
            wmma::fragment<wmma::matrix_b, 16, 16, 16, __half, wmma::row_major> b0, b1;
            wmma::load_matrix_sync(a, &As[(wr * 16) * LDH + ks], LDH);
            wmma::load_matrix_sync(b0, &Ws[ks * LDH + wc * 32], LDH);
            wmma::load_matrix_sync(b1, &Ws[ks * LDH + wc * 32 + 16], LDH);
            wmma::mma_sync(c0, a, b0, c0);
            wmma::mma_sync(c1, a, b1, c1);
        }
        __syncthreads();
    }

    wmma::store_matrix_sync(&Cs[(wr * 16) * 64 + wc * 32],      c0, 64, wmma::mem_row_major);
    wmma::store_matrix_sync(&Cs[(wr * 16) * 64 + wc * 32 + 16], c1, 64, wmma::mem_row_major);
    __syncthreads();

    for (int idx = tid; idx < 64 * 32; idx += 256) {
        int r = idx >> 5, cc = (idx & 31) * 2;
        int row = row0 + r;
        if (row < N_NODES) {
            float di = g_dinv[row];
            g_hs[row * (D/2) + (cc >> 1)] =
                __floats2half2_rn(Cs[r * 64 + cc] * di, Cs[r * 64 + cc + 1] * di);
        }
    }
}

// ---------------- aggregation: warp per node, gather over CSR (fp16 reads) --
__global__ void k_agg(const float* __restrict__ bias) {
    int tid  = threadIdx.x;
    int lane = tid & 31;
    int gw   = (blockIdx.x * blockDim.x + tid) >> 5;
    int nw   = (gridDim.x * blockDim.x) >> 5;

    float b0 = bias[lane * 2];
    float b1 = bias[lane * 2 + 1];
    float s0 = 0.f, s1 = 0.f, q0 = 0.f, q1 = 0.f;

    for (int i = gw; i < N_NODES; i += nw) {
        float2 acc = __half22float2(g_hs[i * (D/2) + lane]);  // self loop
        int rs = g_rowptr[i], re = g_rowptr[i + 1];
        int eb = rs;
        for (; eb + 32 <= re; eb += 32) {
            int myi = g_csr[eb + lane];
            #pragma unroll
            for (int j = 0; j < 32; j++) {
                int s = __shfl_sync(0xffffffffu, myi, j);
                float2 v = __half22float2(g_hs[s * (D/2) + lane]);
                acc.x += v.x; acc.y += v.y;
            }
        }
        if (eb < re) {
            int myi = (eb + lane < re) ? g_csr[eb + lane] : 0;
            int cnt = re - eb;
            for (int j = 0; j < cnt; j++) {
                int s = __shfl_sync(0xffffffffu, myi, j);
                float2 v = __half22float2(g_hs[s * (D/2) + lane]);
                acc.x += v.x; acc.y += v.y;
            }
        }
        float di = g_dinv[i];
        float o0 = acc.x * di + b0;
        float o1 = acc.y * di + b1;
        *(float2*)&g_act[i * D + lane * 2] = make_float2(o0, o1);
        s0 += o0; s1 += o1; q0 += o0 * o0; q1 += o1 * o1;
    }

    __shared__ float ssum[2 * D];
    if (tid < 2 * D) ssum[tid] = 0.f;
    __syncthreads();
    atomicAdd(&ssum[lane * 2],     s0);
    atomicAdd(&ssum[lane * 2 + 1], s1);
    atomicAdd(&ssum[D + lane * 2],     q0);
    atomicAdd(&ssum[D + lane * 2 + 1], q1);
    __syncthreads();
    if (tid < 2 * D) atomicAdd(&g_stats[tid], ssum[tid]);
}

// ---------------- BN scale/shift from stats (also re-zeroes stats) ----------
__global__ void k_st(const float* __restrict__ gamma,
                     const float* __restrict__ beta) {
    int c = threadIdx.x;
    float inv_n = 1.f / (float)N_NODES;
    float mean = g_stats[c] * inv_n;
    float var  = g_stats[D + c] * inv_n - mean * mean;
    float sc = gamma[c] * rsqrtf(var + BN_EPS);
    g_s[c] = sc;
    g_t[c] = beta[c] - mean * sc;
    g_stats[c] = 0.f;
    g_stats[D + c] = 0.f;
}

// ---------------- pooling: segmented accumulation (batch is sorted) ---------
// 256 threads: 4 sub-chunks of 64 nodes; thread (sub, c) accumulates column c.
#define POOL_CHUNK 256
__global__ void k_pool(const int* __restrict__ batch) {
    int tid  = threadIdx.x;
    int c    = tid & 63;
    int sub  = tid >> 6;
    int base = blockIdx.x * POOL_CHUNK + sub * 64;
    int end  = min(base + 64, N_NODES);
    float sc = g_s[c], tc = g_t[c];
    float acc = 0.f;
    int curg = -1;
    for (int n = base; n < end; n++) {
        int g = batch[n];
        float v = fmaxf(g_act[n * D + c] * sc + tc, 0.f);
        if (g != curg) {
            if (curg >= 0) atomicAdd(&g_pool[curg * D + c], acc);
            acc = 0.f; curg = g;
        }
        acc += v;
    }
    if (curg >= 0) atomicAdd(&g_pool[curg * D + c], acc);
}

__global__ void k_final(float* __restrict__ out) {
    int idx = blockIdx.x * blockDim.x + threadIdx.x;
    if (idx < NUM_G * D) {
        int g = idx >> 6;
        out[idx] = g_pool[idx] / fmaxf((float)g_gcnt[g], 1.f);
    }
}

// ---------------- host launch ------------------------------------------------
extern "C" void kernel_launch(void* const* d_in, const int* in_sizes, int n_in,
                              void* d_out, int out_size) {
    const float* x     = (const float*)d_in[0];
    const int*   ei    = (const int*)d_in[1];   // [2, E] int32
    const int*   batch = (const int*)d_in[3];
    const float* W1 = (const float*)d_in[4];
    const float* b1 = (const float*)d_in[5];
    const float* g1 = (const float*)d_in[6];
    const float* be1 = (const float*)d_in[7];
    const float* W2 = (const float*)d_in[8];
    const float* b2 = (const float*)d_in[9];
    const float* g2 = (const float*)d_in[10];
    const float* be2 = (const float*)d_in[11];
    const float* W3 = (const float*)d_in[12];
    const float* b3 = (const float*)d_in[13];
    const float* g3 = (const float*)d_in[14];
    const float* be3 = (const float*)d_in[15];
    float* out = (float*)d_out;

    const int* src = ei;
    const int* dst = ei + N_EDGES;

    const int EB = (N_EDGES + 255) / 256;
    const int NB = (N_NODES + 255) / 256;
    const int GEMM_B = (N_NODES + 63) / 64;

    k_init<<<512, 256>>>();
    k_count<<<EB, 256>>>(dst);
    k_gcnt<<<NB, 256>>>(batch);
    k_scan1<<<NSB, SCAN_TILE>>>();
    k_scan2<<<1, 128>>>();
    k_scan3<<<NB, 256>>>();
    k_fill<<<EB, 256>>>(src, dst);

    // layer 1
    k_gemm<D_IN, false><<<GEMM_B, 256>>>(x, W1);
    k_agg<<<2048, 256>>>(b1);
    k_st<<<1, 64>>>(g1, be1);

    // layer 2
    k_gemm<D, true><<<GEMM_B, 256>>>(nullptr, W2);
    k_agg<<<2048, 256>>>(b2);
    k_st<<<1, 64>>>(g2, be2);

    // layer 3
    k_gemm<D, true><<<GEMM_B, 256>>>(nullptr, W3);
    k_agg<<<2048, 256>>>(b3);
    k_st<<<1, 64>>>(g3, be3);

    // pool + finalize
    k_pool<<<(N_NODES + POOL_CHUNK - 1) / POOL_CHUNK, 256>>>(batch);
    k_final<<<(NUM_G * D + 255) / 256, 256>>>(out);
}